// round 7
// baseline (speedup 1.0000x reference)
#include <cuda_runtime.h>

// Problem dims (fixed)
#define Bc  4
#define Sc  2048
#define Ec  1024
#define Hc  16
#define Dc  64
#define HDc (Hc * Dc)      // 1024
#define Mc  (Bc * Sc)      // 8192

// Scratch
__device__ float g_Q[Bc * Hc * Sc * Dc];
__device__ float g_K[Bc * Hc * Sc * Dc];
__device__ float g_V[Bc * Hc * Sc * Dc];
__device__ float g_AO[Bc * Sc * HDc];        // tf32-rounded by flash epilogue
// tf32-pre-rounded copies (prepass)
__device__ float g_xr [Mc * Ec];
__device__ float g_Wqr[Hc * Ec * Dc];
__device__ float g_Wkr[Hc * Ec * Dc];
__device__ float g_Wvr[Hc * Ec * Dc];
__device__ float g_Wor[HDc * Ec];

// ---------------------------------------------------------------------------
// helpers
// ---------------------------------------------------------------------------
__device__ __forceinline__ unsigned f2tf32(float x) {
    unsigned r;
    asm("cvt.rna.tf32.f32 %0, %1;" : "=r"(r) : "f"(x));
    return r;
}
__device__ __forceinline__ float tf32r(float x) { return __uint_as_float(f2tf32(x)); }

__device__ __forceinline__ void mma8(float* d, const unsigned* a, unsigned b0, unsigned b1) {
    asm volatile(
        "mma.sync.aligned.m16n8k8.row.col.f32.tf32.tf32.f32 "
        "{%0,%1,%2,%3}, {%4,%5,%6,%7}, {%8,%9}, {%0,%1,%2,%3};"
        : "+f"(d[0]), "+f"(d[1]), "+f"(d[2]), "+f"(d[3])
        : "r"(a[0]), "r"(a[1]), "r"(a[2]), "r"(a[3]), "r"(b0), "r"(b1));
}

__device__ __forceinline__ void cp16(void* smem, const void* g) {
    unsigned sa = (unsigned)__cvta_generic_to_shared(smem);
    asm volatile("cp.async.cg.shared.global [%0], [%1], 16;" :: "r"(sa), "l"(g));
}
#define CP_COMMIT asm volatile("cp.async.commit_group;")
#define CP_WAIT0  asm volatile("cp.async.wait_group 0;")

// ---------------------------------------------------------------------------
// Kernel 0: prepass — RNA-round inputs to tf32 once.
// ---------------------------------------------------------------------------
__global__ __launch_bounds__(256) void prepass_kernel(
    const float* __restrict__ x,
    const float* __restrict__ Wq, const float* __restrict__ Wk,
    const float* __restrict__ Wv, const float* __restrict__ Wo)
{
    const float4* src; float4* dst; int n4;
    switch (blockIdx.y) {
        case 0: src = (const float4*)x;  dst = (float4*)g_xr;  n4 = Mc * Ec / 4;      break;
        case 1: src = (const float4*)Wq; dst = (float4*)g_Wqr; n4 = Hc * Ec * Dc / 4; break;
        case 2: src = (const float4*)Wk; dst = (float4*)g_Wkr; n4 = Hc * Ec * Dc / 4; break;
        case 3: src = (const float4*)Wv; dst = (float4*)g_Wvr; n4 = Hc * Ec * Dc / 4; break;
        default:src = (const float4*)Wo; dst = (float4*)g_Wor; n4 = HDc * Ec / 4;     break;
    }
    for (int i = blockIdx.x * blockDim.x + threadIdx.x; i < n4;
         i += gridDim.x * blockDim.x) {
        float4 v = src[i];
        dst[i] = make_float4(tf32r(v.x), tf32r(v.y), tf32r(v.z), tf32r(v.w));
    }
}

// ---------------------------------------------------------------------------
// Kernel 1: FUSED QKV projection. Block 128(M) x 192(N) x 32(K).
// 512 thr = 16 warps (4m x 4n), warp tile 32x48 (acc = 48 regs).
// cp.async double-buffered smem, pre-rounded inputs.
// smem (u32): As0@0 As1@4608 (128x36) | Bs0@9216 Bs1@15616 (32x200)
// ---------------------------------------------------------------------------
#define QKV_AS(buf) ((buf) * 4608)
#define QKV_BS(buf) (9216 + (buf) * 6400)
#define QKV_SMEM_BYTES (22016 * 4)

__global__ __launch_bounds__(512, 1) void qkv_fused_kernel(
    const float* __restrict__ bq, const float* __restrict__ bk,
    const float* __restrict__ bv)
{
    extern __shared__ __align__(16) unsigned smq[];

    const int tid  = threadIdx.x;
    const int warp = tid >> 5, lane = tid & 31;
    const int wm = warp >> 2, wn = warp & 3;     // 4m x 4n
    const int r = lane >> 2, c = lane & 3;
    const int m0 = blockIdx.x * 128;
    const int h  = blockIdx.y;

    const float* __restrict__ Wr[3] = {
        g_Wqr + (size_t)h * Ec * Dc,
        g_Wkr + (size_t)h * Ec * Dc,
        g_Wvr + (size_t)h * Ec * Dc };
    const float* __restrict__ xr = g_xr;

    // stage tile 0 into buf 0
#pragma unroll
    for (int it = 0; it < 2; it++) {
        int i = tid + it * 512; int m = i >> 3; int kq = (i & 7) * 4;
        cp16(&smq[QKV_AS(0) + m * 36 + kq], xr + (size_t)(m0 + m) * Ec + kq);
    }
#pragma unroll
    for (int it = 0; it < 3; it++) {
        int i = tid + it * 512; int kb = i / 48, j = i % 48;
        cp16(&smq[QKV_BS(0) + kb * 200 + j * 4],
             Wr[j >> 4] + (size_t)kb * Dc + (j & 15) * 4);
    }
    CP_COMMIT;

    float acc[2][6][4];
#pragma unroll
    for (int mt = 0; mt < 2; mt++)
#pragma unroll
        for (int nt = 0; nt < 6; nt++)
#pragma unroll
            for (int j = 0; j < 4; j++) acc[mt][nt][j] = 0.0f;

    int buf = 0;
    for (int k0 = 0; k0 < Ec; k0 += 32, buf ^= 1) {
        CP_WAIT0;
        __syncthreads();

        if (k0 + 32 < Ec) {
            int nb = buf ^ 1;
#pragma unroll
            for (int it = 0; it < 2; it++) {
                int i = tid + it * 512; int m = i >> 3; int kq = (i & 7) * 4;
                cp16(&smq[QKV_AS(nb) + m * 36 + kq],
                     xr + (size_t)(m0 + m) * Ec + k0 + 32 + kq);
            }
#pragma unroll
            for (int it = 0; it < 3; it++) {
                int i = tid + it * 512; int kb = i / 48, j = i % 48;
                cp16(&smq[QKV_BS(nb) + kb * 200 + j * 4],
                     Wr[j >> 4] + (size_t)(k0 + 32 + kb) * Dc + (j & 15) * 4);
            }
            CP_COMMIT;
        }

        const unsigned* As = smq + QKV_AS(buf);
        const unsigned* Bs = smq + QKV_BS(buf);
#pragma unroll
        for (int kk = 0; kk < 4; kk++) {
            unsigned af[2][4];
#pragma unroll
            for (int mt = 0; mt < 2; mt++) {
                int R = wm * 32 + mt * 16;
                af[mt][0] = As[(R + r) * 36 + kk * 8 + c];
                af[mt][1] = As[(R + r + 8) * 36 + kk * 8 + c];
                af[mt][2] = As[(R + r) * 36 + kk * 8 + c + 4];
                af[mt][3] = As[(R + r + 8) * 36 + kk * 8 + c + 4];
            }
#pragma unroll
            for (int nt = 0; nt < 6; nt++) {
                int Cn = wn * 48 + nt * 8;
                unsigned b0 = Bs[(kk * 8 + c) * 200 + Cn + r];
                unsigned b1 = Bs[(kk * 8 + c + 4) * 200 + Cn + r];
#pragma unroll
                for (int mt = 0; mt < 2; mt++)
                    mma8(acc[mt][nt], af[mt], b0, b1);
            }
        }
    }

    // epilogue: scatter Q/K/V to [B,H,S,D], tf32-round for flash
    const int bI = m0 >> 11;
    const int sBase = m0 & 2047;
#pragma unroll
    for (int nt = 0; nt < 6; nt++) {
        int g   = wn * 48 + nt * 8;          // 0..191, 8-aligned (never straddles 64)
        int mat = g >> 6;
        int d   = (g & 63) + 2 * c;
        float* Out = (mat == 0) ? g_Q : (mat == 1) ? g_K : g_V;
        const float* bias = (mat == 0) ? bq : (mat == 1) ? bk : bv;
        float bb0 = bias[h * Dc + d], bb1 = bias[h * Dc + d + 1];
#pragma unroll
        for (int mt = 0; mt < 2; mt++) {
            int lr = wm * 32 + mt * 16 + r;
            size_t base = ((((size_t)bI * Hc + h) * Sc) + sBase + lr) * Dc + d;
            *(float2*)(Out + base) =
                make_float2(tf32r(acc[mt][nt][0] + bb0), tf32r(acc[mt][nt][1] + bb1));
            *(float2*)(Out + base + 8 * Dc) =
                make_float2(tf32r(acc[mt][nt][2] + bb0), tf32r(acc[mt][nt][3] + bb1));
        }
    }
}

// ---------------------------------------------------------------------------
// Kernel 3: output projection. Block 128(M) x 128(N) x 32(K).
// 512 thr = 16 warps (4m x 4n), warp tile 32x32 (acc = 32 regs).
// smem (u32): As0@0 As1@4608 | Bs0@9216 Bs1@13568 (32x136) = 17920 u32
// ---------------------------------------------------------------------------
#define O_AS(buf) ((buf) * 4608)
#define O_BS(buf) (9216 + (buf) * 4352)
#define O_SMEM_BYTES (17920 * 4)

__global__ __launch_bounds__(512, 1) void out_gemm_kernel(
    const float* __restrict__ bo, float* __restrict__ outp)
{
    extern __shared__ __align__(16) unsigned smo[];

    const float* __restrict__ A = (const float*)g_AO;
    const float* __restrict__ B = (const float*)g_Wor;

    const int tid  = threadIdx.x;
    const int warp = tid >> 5, lane = tid & 31;
    const int wm = warp >> 2, wn = warp & 3;
    const int r = lane >> 2, c = lane & 3;
    const int m0 = blockIdx.y * 128;
    const int ncol0 = blockIdx.x * 128;

#pragma unroll
    for (int it = 0; it < 2; it++) {
        int i = tid + it * 512; int m = i >> 3; int kq = (i & 7) * 4;
        cp16(&smo[O_AS(0) + m * 36 + kq], A + (size_t)(m0 + m) * HDc + kq);
    }
#pragma unroll
    for (int it = 0; it < 2; it++) {
        int i = tid + it * 512; int kb = i >> 5; int nq = (i & 31) * 4;
        cp16(&smo[O_BS(0) + kb * 136 + nq], B + (size_t)kb * Ec + ncol0 + nq);
    }
    CP_COMMIT;

    float acc[2][4][4];
#pragma unroll
    for (int mt = 0; mt < 2; mt++)
#pragma unroll
        for (int nt = 0; nt < 4; nt++)
#pragma unroll
            for (int j = 0; j < 4; j++) acc[mt][nt][j] = 0.0f;

    int buf = 0;
    for (int k0 = 0; k0 < HDc; k0 += 32, buf ^= 1) {
        CP_WAIT0;
        __syncthreads();

        if (k0 + 32 < HDc) {
            int nb = buf ^ 1;
#pragma unroll
            for (int it = 0; it < 2; it++) {
                int i = tid + it * 512; int m = i >> 3; int kq = (i & 7) * 4;
                cp16(&smo[O_AS(nb) + m * 36 + kq],
                     A + (size_t)(m0 + m) * HDc + k0 + 32 + kq);
            }
#pragma unroll
            for (int it = 0; it < 2; it++) {
                int i = tid + it * 512; int kb = i >> 5; int nq = (i & 31) * 4;
                cp16(&smo[O_BS(nb) + kb * 136 + nq],
                     B + (size_t)(k0 + 32 + kb) * Ec + ncol0 + nq);
            }
            CP_COMMIT;
        }

        const unsigned* As = smo + O_AS(buf);
        const unsigned* Bs = smo + O_BS(buf);
#pragma unroll
        for (int kk = 0; kk < 4; kk++) {
            unsigned af[2][4];
#pragma unroll
            for (int mt = 0; mt < 2; mt++) {
                int R = wm * 32 + mt * 16;
                af[mt][0] = As[(R + r) * 36 + kk * 8 + c];
                af[mt][1] = As[(R + r + 8) * 36 + kk * 8 + c];
                af[mt][2] = As[(R + r) * 36 + kk * 8 + c + 4];
                af[mt][3] = As[(R + r + 8) * 36 + kk * 8 + c + 4];
            }
#pragma unroll
            for (int nt = 0; nt < 4; nt++) {
                int Cn = wn * 32 + nt * 8;
                unsigned b0 = Bs[(kk * 8 + c) * 136 + Cn + r];
                unsigned b1 = Bs[(kk * 8 + c + 4) * 136 + Cn + r];
#pragma unroll
                for (int mt = 0; mt < 2; mt++)
                    mma8(acc[mt][nt], af[mt], b0, b1);
            }
        }
    }

#pragma unroll
    for (int mt = 0; mt < 2; mt++) {
        int mrow = m0 + wm * 32 + mt * 16 + r;
#pragma unroll
        for (int nt = 0; nt < 4; nt++) {
            int d = ncol0 + wn * 32 + nt * 8 + 2 * c;
            float bb0 = bo[d], bb1 = bo[d + 1];
            *(float2*)(outp + (size_t)mrow * Ec + d) =
                make_float2(acc[mt][nt][0] + bb0, acc[mt][nt][1] + bb1);
            *(float2*)(outp + (size_t)(mrow + 8) * Ec + d) =
                make_float2(acc[mt][nt][2] + bb0, acc[mt][nt][3] + bb1);
        }
    }
}

// ---------------------------------------------------------------------------
// Kernel 2: flash attention (tf32 HMMA). BQ=128 (8 warps, 16 q-rows each),
// BKT=64, D=64. K/V cp.async double-buffered; K/V traffic halved vs BQ=64.
// Warp-uniform causal early-out skips fully-masked tiles.
// smem (u32): buf0 Ks@0 (64*68) Vs@4352 (64*72) | buf1 Ks@8960 Vs@13312
//             Ps@17920 + warp*1088 (16*68) x 8 -> 26624 u32 = 106496 B
// Q (128x68 = 8704 u32) staged transiently in buf0 region before the loop.
// ---------------------------------------------------------------------------
#define PS_LD   68
#define PS_BASE 17920
#define SMEM_BYTES (26624 * 4)

__device__ __forceinline__ void stage_kv(unsigned* Ksb, unsigned* Vsb,
                                         const float* Kb, const float* Vb,
                                         int k0, int tid)
{
#pragma unroll
    for (int it = 0; it < 4; it++) {
        int i = tid + it * 256;
        int row = i >> 4;
        int cq = (i & 15) * 4;
        cp16(&Ksb[row * 68 + cq], Kb + (size_t)(k0 + row) * Dc + cq);
        cp16(&Vsb[row * 72 + cq], Vb + (size_t)(k0 + row) * Dc + cq);
    }
}

__global__ __launch_bounds__(256, 2) void flash_tf32_kernel()
{
    extern __shared__ __align__(16) unsigned sm[];

    const int bh = blockIdx.y;
    const int b  = bh >> 4, h = bh & 15;
    const int q0 = blockIdx.x * 128;

    const float* __restrict__ Qb = g_Q + (size_t)bh * Sc * Dc;
    const float* __restrict__ Kb = g_K + (size_t)bh * Sc * Dc;
    const float* __restrict__ Vb = g_V + (size_t)bh * Sc * Dc;

    const int tid  = threadIdx.x;
    const int warp = tid >> 5, lane = tid & 31;
    const int r = lane >> 2, c = lane & 3;

    // stage Q (128x64) through buf0 region, extract A-fragments
#pragma unroll
    for (int it = 0; it < 8; it++) {
        int i = tid + it * 256;
        int row = i >> 4, cq = (i & 15) * 4;
        *(uint4*)&sm[row * 68 + cq] = *(const uint4*)(Qb + (size_t)(q0 + row) * Dc + cq);
    }
    __syncthreads();
    unsigned qf[8][4];
    {
        int R = warp * 16;
#pragma unroll
        for (int kk = 0; kk < 8; kk++) {
            qf[kk][0] = sm[(R + r) * 68 + kk * 8 + c];
            qf[kk][1] = sm[(R + r + 8) * 68 + kk * 8 + c];
            qf[kk][2] = sm[(R + r) * 68 + kk * 8 + c + 4];
            qf[kk][3] = sm[(R + r + 8) * 68 + kk * 8 + c + 4];
        }
    }
    __syncthreads();

    unsigned* Ps = sm + PS_BASE + warp * (16 * PS_LD);

    const int nkt = 2 * (blockIdx.x + 1);     // 64-wide k tiles covering q0+128
    stage_kv(sm, sm + 4352, Kb, Vb, 0, tid);
    CP_COMMIT;

    float of[8][4];
#pragma unroll
    for (int nt = 0; nt < 8; nt++)
#pragma unroll
        for (int j = 0; j < 4; j++) of[nt][j] = 0.0f;
    float m_lo = -1e30f, m_hi = -1e30f, l_lo = 0.0f, l_hi = 0.0f;

    const int qlo = q0 + warp * 16 + r;
    const int qhi = qlo + 8;
    const int qmax = q0 + warp * 16 + 15;     // warp-uniform

    int buf = 0;
    for (int kt = 0; kt < nkt; kt++) {
        CP_WAIT0;
        __syncthreads();
        if (kt + 1 < nkt) {
            int nb = buf ^ 1;
            stage_kv(sm + nb * 8960, sm + nb * 8960 + 4352, Kb, Vb, (kt + 1) * 64, tid);
            CP_COMMIT;
        }
        const int kbase = kt * 64;
        if (kbase <= qmax) {                   // skip fully-masked tiles (warp-uniform)
            unsigned* Ksb = sm + buf * 8960;
            unsigned* Vsb = Ksb + 4352;

            // S = Q K^T
            float sf[8][4];
#pragma unroll
            for (int nt = 0; nt < 8; nt++) {
                sf[nt][0] = sf[nt][1] = sf[nt][2] = sf[nt][3] = 0.0f;
#pragma unroll
                for (int kk = 0; kk < 8; kk++) {
                    unsigned b0 = Ksb[(nt * 8 + r) * 68 + kk * 8 + c];
                    unsigned b1 = Ksb[(nt * 8 + r) * 68 + kk * 8 + c + 4];
                    mma8(sf[nt], qf[kk], b0, b1);
                }
            }

            // scale + causal mask + online softmax
            float mx_lo = -1e30f, mx_hi = -1e30f;
#pragma unroll
            for (int nt = 0; nt < 8; nt++) {
                int kg0 = kbase + nt * 8 + 2 * c;
                int kg1 = kg0 + 1;
                float s0 = sf[nt][0] * 0.125f; if (kg0 > qlo) s0 = -1e30f;
                float s1 = sf[nt][1] * 0.125f; if (kg1 > qlo) s1 = -1e30f;
                float s2 = sf[nt][2] * 0.125f; if (kg0 > qhi) s2 = -1e30f;
                float s3 = sf[nt][3] * 0.125f; if (kg1 > qhi) s3 = -1e30f;
                sf[nt][0] = s0; sf[nt][1] = s1; sf[nt][2] = s2; sf[nt][3] = s3;
                mx_lo = fmaxf(mx_lo, fmaxf(s0, s1));
                mx_hi = fmaxf(mx_hi, fmaxf(s2, s3));
            }
            mx_lo = fmaxf(mx_lo, __shfl_xor_sync(0xffffffffu, mx_lo, 1));
            mx_lo = fmaxf(mx_lo, __shfl_xor_sync(0xffffffffu, mx_lo, 2));
            mx_hi = fmaxf(mx_hi, __shfl_xor_sync(0xffffffffu, mx_hi, 1));
            mx_hi = fmaxf(mx_hi, __shfl_xor_sync(0xffffffffu, mx_hi, 2));

            float mn_lo = fmaxf(m_lo, mx_lo), mn_hi = fmaxf(m_hi, mx_hi);
            float a_lo = __expf(m_lo - mn_lo), a_hi = __expf(m_hi - mn_hi);

            float ps_lo = 0.0f, ps_hi = 0.0f;
#pragma unroll
            for (int nt = 0; nt < 8; nt++) {
                float p0 = __expf(sf[nt][0] - mn_lo);
                float p1 = __expf(sf[nt][1] - mn_lo);
                float p2 = __expf(sf[nt][2] - mn_hi);
                float p3 = __expf(sf[nt][3] - mn_hi);
                ps_lo += p0 + p1;  ps_hi += p2 + p3;
                *(uint2*)&Ps[r * PS_LD + nt * 8 + 2 * c]       = make_uint2(f2tf32(p0), f2tf32(p1));
                *(uint2*)&Ps[(r + 8) * PS_LD + nt * 8 + 2 * c] = make_uint2(f2tf32(p2), f2tf32(p3));
            }
            ps_lo += __shfl_xor_sync(0xffffffffu, ps_lo, 1);
            ps_lo += __shfl_xor_sync(0xffffffffu, ps_lo, 2);
            ps_hi += __shfl_xor_sync(0xffffffffu, ps_hi, 1);
            ps_hi += __shfl_xor_sync(0xffffffffu, ps_hi, 2);
            l_lo = l_lo * a_lo + ps_lo;
            l_hi = l_hi * a_hi + ps_hi;
            m_lo = mn_lo; m_hi = mn_hi;

#pragma unroll
            for (int nt = 0; nt < 8; nt++) {
                of[nt][0] *= a_lo; of[nt][1] *= a_lo;
                of[nt][2] *= a_hi; of[nt][3] *= a_hi;
            }
            __syncwarp();

            // O += P V
#pragma unroll
            for (int kk = 0; kk < 8; kk++) {
                unsigned pf[4];
                pf[0] = Ps[r * PS_LD + kk * 8 + c];
                pf[1] = Ps[(r + 8) * PS_LD + kk * 8 + c];
                pf[2] = Ps[r * PS_LD + kk * 8 + c + 4];
                pf[3] = Ps[(r + 8) * PS_LD + kk * 8 + c + 4];
#pragma unroll
                for (int nt = 0; nt < 8; nt++) {
                    unsigned b0 = Vsb[(kk * 8 + c) * 72 + nt * 8 + r];
                    unsigned b1 = Vsb[(kk * 8 + c + 4) * 72 + nt * 8 + r];
                    mma8(of[nt], pf, b0, b1);
                }
            }
        }
        buf ^= 1;
    }

    // epilogue: normalize, tf32-round, write AO [B,S,H*D]
    float il_lo = 1.0f / l_lo, il_hi = 1.0f / l_hi;
    size_t rb_lo = ((size_t)b * Sc + qlo) * HDc + h * Dc;
    size_t rb_hi = ((size_t)b * Sc + qhi) * HDc + h * Dc;
#pragma unroll
    for (int nt = 0; nt < 8; nt++) {
        int d = nt * 8 + 2 * c;
        *(float2*)(g_AO + rb_lo + d) =
            make_float2(tf32r(of[nt][0] * il_lo), tf32r(of[nt][1] * il_lo));
        *(float2*)(g_AO + rb_hi + d) =
            make_float2(tf32r(of[nt][2] * il_hi), tf32r(of[nt][3] * il_hi));
    }
}

// ---------------------------------------------------------------------------
extern "C" void kernel_launch(void* const* d_in, const int* in_sizes, int n_in,
                              void* d_out, int out_size)
{
    const float* x  = (const float*)d_in[0];
    const float* Wq = (const float*)d_in[1];
    const float* bq = (const float*)d_in[2];
    const float* Wk = (const float*)d_in[3];
    const float* bk = (const float*)d_in[4];
    const float* Wv = (const float*)d_in[5];
    const float* bv = (const float*)d_in[6];
    const float* Wo = (const float*)d_in[7];
    const float* bo = (const float*)d_in[8];
    float* out = (float*)d_out;

    cudaFuncSetAttribute(qkv_fused_kernel,
                         cudaFuncAttributeMaxDynamicSharedMemorySize, QKV_SMEM_BYTES);
    cudaFuncSetAttribute(flash_tf32_kernel,
                         cudaFuncAttributeMaxDynamicSharedMemorySize, SMEM_BYTES);
    cudaFuncSetAttribute(out_gemm_kernel,
                         cudaFuncAttributeMaxDynamicSharedMemorySize, O_SMEM_BYTES);

    dim3 g0(448, 5);
    prepass_kernel<<<g0, 256>>>(x, Wq, Wk, Wv, Wo);

    dim3 g1(Mc / 128, Hc);
    qkv_fused_kernel<<<g1, 512, QKV_SMEM_BYTES>>>(bq, bk, bv);

    dim3 g2(Sc / 128, Bc * Hc);
    flash_tf32_kernel<<<g2, 256, SMEM_BYTES>>>();

    dim3 g3(Ec / 128, Mc / 128);
    out_gemm_kernel<<<g3, 512, O_SMEM_BYTES>>>(bo, out);
}